// round 3
// baseline (speedup 1.0000x reference)
#include <cuda_runtime.h>
#include <cuda_bf16.h>
#include <math.h>

// Problem dims (fixed by reference setup_inputs)
constexpr int Bc = 32;
constexpr int Tc = 4;
constexpr int Lc = 196;
constexpr int Dc = 384;
constexpr int Hc = 1536;
constexpr int Mrows = Tc * Bc * Lc;   // 25088

// Scratch (device globals; allocation-free per harness rules)
__device__ float g_h1[(size_t)Mrows * Hc];   // pre-LN GEMM1 output  (~154 MB)
__device__ float g_s1[(size_t)Mrows * Hc];   // spikes layer 1       (~154 MB)
__device__ float g_h2[(size_t)Mrows * Dc];   // pre-LN GEMM2 output  (~38 MB)

// ---------------------------------------------------------------------------
// Block reduce of one f64 value, result broadcast to all threads.
// f64 accumulation kills reduction-order noise (<=1e-9 rel) so we don't have
// to replicate XLA's reduce ordering bit-for-bit.
// ---------------------------------------------------------------------------
__device__ __forceinline__ double block_reduce_d(double a) {
    __shared__ double sa[32];
    const unsigned m = 0xffffffffu;
#pragma unroll
    for (int o = 16; o; o >>= 1) a += __shfl_down_sync(m, a, o);
    const int lane = threadIdx.x & 31, w = threadIdx.x >> 5;
    __syncthreads();              // protect shared reuse across calls
    if (lane == 0) sa[w] = a;
    __syncthreads();
    const int nw = blockDim.x >> 5;
    if (w == 0) {
        a = (lane < nw) ? sa[lane] : 0.0;
#pragma unroll
        for (int o = 16; o; o >>= 1) a += __shfl_down_sync(m, a, o);
        if (lane == 0) sa[0] = a;
    }
    __syncthreads();
    return sa[0];
}

// ---------------------------------------------------------------------------
// GEMM1: h1pre[r, h] = b1[h] + sum_d x[b,t,l,d] * W1[h,d]
// Strictly ascending-k fp32 FMA chain per output element (matches the
// Eigen / cuBLAS SGEMM accumulation order), bias added as one separate FADD.
// Tiles: BM=64, BN=64, BK=16, 256 threads, 4x4 per thread. All dims exact.
// ---------------------------------------------------------------------------
__global__ __launch_bounds__(256) void gemm1_kernel(
    const float* __restrict__ x, const float* __restrict__ W1,
    const float* __restrict__ b1) {
    constexpr int BM = 64, BN = 64, BK = 16;
    __shared__ float As[BK][BM];
    __shared__ float Bs[BK][BN];

    const int tid = threadIdx.x;
    const int row = tid >> 2;          // 0..63
    const int c4  = (tid & 3) * 4;     // 0,4,8,12

    // A row mapping (x is [B,T,L,D] but r enumerates (t,b,l))
    const int r = blockIdx.x * BM + row;
    const int l  = r % Lc;
    const int tb = r / Lc;
    const int bI = tb % Bc;
    const int tI = tb / Bc;
    const float* aptr = x  + (size_t)((bI * Tc + tI) * Lc + l) * Dc + c4;
    const float* bptr = W1 + (size_t)(blockIdx.y * BN + row) * Dc + c4;

    const int tx = tid & 15;   // n
    const int ty = tid >> 4;   // m
    float acc[4][4] = {};

    for (int k0 = 0; k0 < Dc; k0 += BK) {
        const float4 av = *(const float4*)(aptr + k0);
        const float4 bv = *(const float4*)(bptr + k0);
        __syncthreads();
        As[c4 + 0][row] = av.x; As[c4 + 1][row] = av.y;
        As[c4 + 2][row] = av.z; As[c4 + 3][row] = av.w;
        Bs[c4 + 0][row] = bv.x; Bs[c4 + 1][row] = bv.y;
        Bs[c4 + 2][row] = bv.z; Bs[c4 + 3][row] = bv.w;
        __syncthreads();
#pragma unroll
        for (int k = 0; k < BK; k++) {
            const float4 a4 = *(const float4*)&As[k][ty * 4];
            const float4 b4 = *(const float4*)&Bs[k][tx * 4];
#pragma unroll
            for (int i = 0; i < 4; i++) {
                const float a = (i == 0) ? a4.x : (i == 1) ? a4.y : (i == 2) ? a4.z : a4.w;
                acc[i][0] = __fmaf_rn(a, b4.x, acc[i][0]);
                acc[i][1] = __fmaf_rn(a, b4.y, acc[i][1]);
                acc[i][2] = __fmaf_rn(a, b4.z, acc[i][2]);
                acc[i][3] = __fmaf_rn(a, b4.w, acc[i][3]);
            }
        }
    }

    const int h = blockIdx.y * BN + tx * 4;
    const float4 bb = *(const float4*)(b1 + h);
#pragma unroll
    for (int i = 0; i < 4; i++) {
        float4 o;
        o.x = __fadd_rn(acc[i][0], bb.x); o.y = __fadd_rn(acc[i][1], bb.y);
        o.z = __fadd_rn(acc[i][2], bb.z); o.w = __fadd_rn(acc[i][3], bb.w);
        *(float4*)(g_h1 + (size_t)(blockIdx.x * BM + ty * 4 + i) * Hc + h) = o;
    }
}

// ---------------------------------------------------------------------------
// GEMM2: h2pre[r, d] = b2[d] + sum_h s1[r, h] * W2[d, h]
// ---------------------------------------------------------------------------
__global__ __launch_bounds__(256) void gemm2_kernel(
    const float* __restrict__ W2, const float* __restrict__ b2) {
    constexpr int BM = 64, BN = 64, BK = 16;
    __shared__ float As[BK][BM];
    __shared__ float Bs[BK][BN];

    const int tid = threadIdx.x;
    const int row = tid >> 2;
    const int c4  = (tid & 3) * 4;

    const float* aptr = g_s1 + (size_t)(blockIdx.x * BM + row) * Hc + c4;
    const float* bptr = W2   + (size_t)(blockIdx.y * BN + row) * Hc + c4;

    const int tx = tid & 15;
    const int ty = tid >> 4;
    float acc[4][4] = {};

    for (int k0 = 0; k0 < Hc; k0 += BK) {
        const float4 av = *(const float4*)(aptr + k0);
        const float4 bv = *(const float4*)(bptr + k0);
        __syncthreads();
        As[c4 + 0][row] = av.x; As[c4 + 1][row] = av.y;
        As[c4 + 2][row] = av.z; As[c4 + 3][row] = av.w;
        Bs[c4 + 0][row] = bv.x; Bs[c4 + 1][row] = bv.y;
        Bs[c4 + 2][row] = bv.z; Bs[c4 + 3][row] = bv.w;
        __syncthreads();
#pragma unroll
        for (int k = 0; k < BK; k++) {
            const float4 a4 = *(const float4*)&As[k][ty * 4];
            const float4 b4 = *(const float4*)&Bs[k][tx * 4];
#pragma unroll
            for (int i = 0; i < 4; i++) {
                const float a = (i == 0) ? a4.x : (i == 1) ? a4.y : (i == 2) ? a4.z : a4.w;
                acc[i][0] = __fmaf_rn(a, b4.x, acc[i][0]);
                acc[i][1] = __fmaf_rn(a, b4.y, acc[i][1]);
                acc[i][2] = __fmaf_rn(a, b4.z, acc[i][2]);
                acc[i][3] = __fmaf_rn(a, b4.w, acc[i][3]);
            }
        }
    }

    const int d = blockIdx.y * BN + tx * 4;
    const float4 bb = *(const float4*)(b2 + d);
#pragma unroll
    for (int i = 0; i < 4; i++) {
        float4 o;
        o.x = __fadd_rn(acc[i][0], bb.x); o.y = __fadd_rn(acc[i][1], bb.y);
        o.z = __fadd_rn(acc[i][2], bb.z); o.w = __fadd_rn(acc[i][3], bb.w);
        *(float4*)(g_h2 + (size_t)(blockIdx.x * BM + ty * 4 + i) * Dc + d) = o;
    }
}

// ---------------------------------------------------------------------------
// Fused LayerNorm + LIF. Exact replication of the reference's f32 op sequence:
//   mu  = sum(x)/H                      (true division)
//   var = sum(f32((x-mu)^2))/H          (two-pass, per-element f32 rounding)
//   y   = ((x-mu)*rsqrt)*g + b          (separate roundings, no contraction)
//   rsqrt = 1.0f / sqrtf(var+eps)       (two correctly-rounded ops)
//   v   = v + (y - v)*0.5f ; s = v>=1 ; v *= (1-s)
// ---------------------------------------------------------------------------
__global__ __launch_bounds__(256) void ln_lif1_kernel(
    const float* __restrict__ g1, const float* __restrict__ be1) {
    constexpr int PER = Hc / 256;   // 6
    const int bl = blockIdx.x;
    const int bI = bl / Lc, l = bl % Lc;
    const int tid = threadIdx.x;

    float v[PER], gg[PER], bb[PER];
#pragma unroll
    for (int i = 0; i < PER; i++) {
        v[i] = 0.f;
        gg[i] = g1[tid + i * 256];
        bb[i] = be1[tid + i * 256];
    }

    for (int t = 0; t < Tc; t++) {
        const size_t base = (size_t)((t * Bc + bI) * Lc + l) * Hc;
        float y[PER];
        double s = 0.0;
#pragma unroll
        for (int i = 0; i < PER; i++) {
            y[i] = g_h1[base + tid + i * 256];
            s += (double)y[i];
        }
        s = block_reduce_d(s);
        const float mu = (float)(s / (double)Hc);

        double s2 = 0.0;
#pragma unroll
        for (int i = 0; i < PER; i++) {
            const float d  = __fsub_rn(y[i], mu);
            const float sq = __fmul_rn(d, d);
            s2 += (double)sq;
        }
        s2 = block_reduce_d(s2);
        const float var  = (float)(s2 / (double)Hc);
        const float rstd = __fdiv_rn(1.0f, __fsqrt_rn(__fadd_rn(var, 1e-5f)));

#pragma unroll
        for (int i = 0; i < PER; i++) {
            const float yy = __fadd_rn(
                __fmul_rn(__fmul_rn(__fsub_rn(y[i], mu), rstd), gg[i]), bb[i]);
            v[i] = __fadd_rn(v[i], __fmul_rn(__fsub_rn(yy, v[i]), 0.5f));
            const float sp = (v[i] >= 1.0f) ? 1.f : 0.f;
            g_s1[base + tid + i * 256] = sp;
            v[i] = __fmul_rn(v[i], __fsub_rn(1.0f, sp));
        }
    }
}

__global__ __launch_bounds__(128) void ln_lif2_kernel(
    const float* __restrict__ g2, const float* __restrict__ be2,
    float* __restrict__ out) {
    constexpr int PER = Dc / 128;   // 3
    const int bl = blockIdx.x;
    const int bI = bl / Lc, l = bl % Lc;
    const int tid = threadIdx.x;

    float v[PER], gg[PER], bb[PER];
#pragma unroll
    for (int i = 0; i < PER; i++) {
        v[i] = 0.f;
        gg[i] = g2[tid + i * 128];
        bb[i] = be2[tid + i * 128];
    }

    for (int t = 0; t < Tc; t++) {
        const size_t base  = (size_t)((t * Bc + bI) * Lc + l) * Dc;
        const size_t obase = (size_t)((bI * Tc + t) * Lc + l) * Dc;
        float y[PER];
        double s = 0.0;
#pragma unroll
        for (int i = 0; i < PER; i++) {
            y[i] = g_h2[base + tid + i * 128];
            s += (double)y[i];
        }
        s = block_reduce_d(s);
        const float mu = (float)(s / (double)Dc);

        double s2 = 0.0;
#pragma unroll
        for (int i = 0; i < PER; i++) {
            const float d  = __fsub_rn(y[i], mu);
            const float sq = __fmul_rn(d, d);
            s2 += (double)sq;
        }
        s2 = block_reduce_d(s2);
        const float var  = (float)(s2 / (double)Dc);
        const float rstd = __fdiv_rn(1.0f, __fsqrt_rn(__fadd_rn(var, 1e-5f)));

#pragma unroll
        for (int i = 0; i < PER; i++) {
            const float yy = __fadd_rn(
                __fmul_rn(__fmul_rn(__fsub_rn(y[i], mu), rstd), gg[i]), bb[i]);
            v[i] = __fadd_rn(v[i], __fmul_rn(__fsub_rn(yy, v[i]), 0.5f));
            const float sp = (v[i] >= 1.0f) ? 1.f : 0.f;
            out[obase + tid + i * 128] = sp;
            v[i] = __fmul_rn(v[i], __fsub_rn(1.0f, sp));
        }
    }
}

// ---------------------------------------------------------------------------
extern "C" void kernel_launch(void* const* d_in, const int* in_sizes, int n_in,
                              void* d_out, int out_size) {
    const float* x   = (const float*)d_in[0];
    const float* W1  = (const float*)d_in[1];
    const float* b1  = (const float*)d_in[2];
    const float* g1  = (const float*)d_in[3];
    const float* be1 = (const float*)d_in[4];
    const float* W2  = (const float*)d_in[5];
    const float* b2  = (const float*)d_in[6];
    const float* g2  = (const float*)d_in[7];
    const float* be2 = (const float*)d_in[8];
    float* out = (float*)d_out;

    gemm1_kernel<<<dim3(Mrows / 64, Hc / 64), 256>>>(x, W1, b1);
    ln_lif1_kernel<<<Bc * Lc, 256>>>(g1, be1);
    gemm2_kernel<<<dim3(Mrows / 64, Dc / 64), 256>>>(W2, b2);
    ln_lif2_kernel<<<Bc * Lc, 128>>>(g2, be2, out);
}

// round 4
// speedup vs baseline: 1.4597x; 1.4597x over previous
#include <cuda_runtime.h>
#include <cuda_bf16.h>
#include <math.h>

// Problem dims (fixed by reference setup_inputs)
constexpr int Bc = 32;
constexpr int Tc = 4;
constexpr int Lc = 196;
constexpr int Dc = 384;
constexpr int Hc = 1536;
constexpr int Mrows = Tc * Bc * Lc;   // 25088

// Scratch (device globals; allocation-free per harness rules)
__device__ float g_h1[(size_t)Mrows * Hc];   // pre-LN GEMM1 output  (~154 MB)
__device__ float g_s1[(size_t)Mrows * Hc];   // spikes layer 1       (~154 MB)
__device__ float g_h2[(size_t)Mrows * Dc];   // pre-LN GEMM2 output  (~38 MB)
__device__ float g_mu1[Mrows], g_rs1[Mrows];
__device__ float g_mu2[Mrows], g_rs2[Mrows];

// ---------------------------------------------------------------------------
// GEMM core: 128x128 tile, BK=8, 256 threads, 8x8 per thread, double-buffered.
// Bit-exactness contract: each output element is ONE fp32 FMA chain with k
// strictly ascending 0..K-1 (matches the reference einsum), bias added as a
// single separate __fadd_rn at the end.
// blockIdx.x = N-block (small), blockIdx.y = M-block  -> consecutive CTAs
// share the A block and the whole weight matrix through L2.
// ---------------------------------------------------------------------------
#define GEMM_BODY(K_DIM, APTR_EXPR, BPTR_EXPR, BIAS, OUTBASE, OUT_LD)          \
    constexpr int BK = 8;                                                      \
    __shared__ float As[2][BK][128];                                           \
    __shared__ float Bs[2][BK][128];                                           \
    const int tid = threadIdx.x;                                               \
    const int lr = tid >> 1;                                                   \
    const int lc = (tid & 1) * 4;                                              \
    const float* aptr = (APTR_EXPR);                                           \
    const float* bptr = (BPTR_EXPR);                                           \
    const int tx = tid & 15;                                                   \
    const int ty = tid >> 4;                                                   \
    float acc[8][8] = {};                                                      \
    float4 av = *(const float4*)aptr;                                          \
    float4 bv = *(const float4*)bptr;                                          \
    int buf = 0;                                                               \
    As[0][lc + 0][lr] = av.x; As[0][lc + 1][lr] = av.y;                        \
    As[0][lc + 2][lr] = av.z; As[0][lc + 3][lr] = av.w;                        \
    Bs[0][lc + 0][lr] = bv.x; Bs[0][lc + 1][lr] = bv.y;                        \
    Bs[0][lc + 2][lr] = bv.z; Bs[0][lc + 3][lr] = bv.w;                        \
    __syncthreads();                                                           \
    for (int k0 = BK; k0 < (K_DIM) + BK; k0 += BK) {                           \
        const bool more = (k0 < (K_DIM));                                      \
        if (more) {                                                            \
            av = *(const float4*)(aptr + k0);                                  \
            bv = *(const float4*)(bptr + k0);                                  \
        }                                                                      \
        _Pragma("unroll")                                                      \
        for (int k = 0; k < BK; k++) {                                         \
            const float4 a0 = *(const float4*)&As[buf][k][ty * 8];             \
            const float4 a1 = *(const float4*)&As[buf][k][ty * 8 + 4];         \
            const float4 b0 = *(const float4*)&Bs[buf][k][tx * 8];             \
            const float4 b1 = *(const float4*)&Bs[buf][k][tx * 8 + 4];         \
            const float am[8] = {a0.x, a0.y, a0.z, a0.w, a1.x, a1.y, a1.z, a1.w}; \
            const float bn[8] = {b0.x, b0.y, b0.z, b0.w, b1.x, b1.y, b1.z, b1.w}; \
            _Pragma("unroll")                                                  \
            for (int i = 0; i < 8; i++) {                                      \
                _Pragma("unroll")                                              \
                for (int j = 0; j < 8; j++)                                    \
                    acc[i][j] = __fmaf_rn(am[i], bn[j], acc[i][j]);            \
            }                                                                  \
        }                                                                      \
        if (more) {                                                            \
            buf ^= 1;                                                          \
            As[buf][lc + 0][lr] = av.x; As[buf][lc + 1][lr] = av.y;            \
            As[buf][lc + 2][lr] = av.z; As[buf][lc + 3][lr] = av.w;            \
            Bs[buf][lc + 0][lr] = bv.x; Bs[buf][lc + 1][lr] = bv.y;            \
            Bs[buf][lc + 2][lr] = bv.z; Bs[buf][lc + 3][lr] = bv.w;            \
            __syncthreads();                                                   \
        }                                                                      \
    }                                                                          \
    const int n0 = blockIdx.x * 128 + tx * 8;                                  \
    const float4 bb0 = *(const float4*)((BIAS) + n0);                          \
    const float4 bb1 = *(const float4*)((BIAS) + n0 + 4);                      \
    const int m0 = blockIdx.y * 128 + ty * 8;                                  \
    _Pragma("unroll")                                                          \
    for (int i = 0; i < 8; i++) {                                              \
        float* o = (OUTBASE) + (size_t)(m0 + i) * (OUT_LD) + n0;               \
        float4 o0, o1;                                                         \
        o0.x = __fadd_rn(acc[i][0], bb0.x); o0.y = __fadd_rn(acc[i][1], bb0.y);\
        o0.z = __fadd_rn(acc[i][2], bb0.z); o0.w = __fadd_rn(acc[i][3], bb0.w);\
        o1.x = __fadd_rn(acc[i][4], bb1.x); o1.y = __fadd_rn(acc[i][5], bb1.y);\
        o1.z = __fadd_rn(acc[i][6], bb1.z); o1.w = __fadd_rn(acc[i][7], bb1.w);\
        *(float4*)o = o0;                                                      \
        *(float4*)(o + 4) = o1;                                                \
    }

__global__ __launch_bounds__(256) void gemm1_kernel(
    const float* __restrict__ x, const float* __restrict__ W1,
    const float* __restrict__ b1) {
    // A row r = (t*B + b)*L + l maps into x at ((b*T + t)*L + l)*D
    const int r_ = blockIdx.y * 128 + (threadIdx.x >> 1);
    const int l_  = r_ % Lc;
    const int tb_ = r_ / Lc;
    const int bI_ = tb_ % Bc;
    const int tI_ = tb_ / Bc;
    GEMM_BODY(Dc,
              x  + (size_t)((bI_ * Tc + tI_) * Lc + l_) * Dc + ((threadIdx.x & 1) * 4),
              W1 + (size_t)(blockIdx.x * 128 + (threadIdx.x >> 1)) * Dc + ((threadIdx.x & 1) * 4),
              b1, g_h1, Hc)
}

__global__ __launch_bounds__(256) void gemm2_kernel(
    const float* __restrict__ W2, const float* __restrict__ b2) {
    GEMM_BODY(Hc,
              g_s1 + (size_t)(blockIdx.y * 128 + (threadIdx.x >> 1)) * Hc + ((threadIdx.x & 1) * 4),
              W2   + (size_t)(blockIdx.x * 128 + (threadIdx.x >> 1)) * Hc + ((threadIdx.x & 1) * 4),
              b2, g_h2, Dc)
}

// ---------------------------------------------------------------------------
// Row statistics: one warp per row, row held in registers, f64 butterfly
// reduce (no barriers). Same arithmetic as before:
//   mu  = f32( f64sum(y) / N )
//   var = f32( f64sum( f32((y-mu)^2) ) / N )
//   rstd = 1.0f / sqrtf(var + 1e-5f)
// ---------------------------------------------------------------------------
template <int NC>
__global__ __launch_bounds__(256) void stats_kernel(
    const float* __restrict__ src, float* __restrict__ muA,
    float* __restrict__ rsA) {
    const int row = blockIdx.x * 8 + (threadIdx.x >> 5);
    const int lane = threadIdx.x & 31;
    const float* p = src + (size_t)row * NC;
    constexpr int J = NC / 128;
    float4 y[J];
    double s = 0.0;
#pragma unroll
    for (int j = 0; j < J; j++) {
        y[j] = *(const float4*)(p + lane * 4 + j * 128);
        s += (double)y[j].x; s += (double)y[j].y;
        s += (double)y[j].z; s += (double)y[j].w;
    }
#pragma unroll
    for (int o = 16; o; o >>= 1) s += __shfl_xor_sync(0xffffffffu, s, o);
    const float mu = (float)(s / (double)NC);

    double s2 = 0.0;
#pragma unroll
    for (int j = 0; j < J; j++) {
        float d;
        d = __fsub_rn(y[j].x, mu); s2 += (double)__fmul_rn(d, d);
        d = __fsub_rn(y[j].y, mu); s2 += (double)__fmul_rn(d, d);
        d = __fsub_rn(y[j].z, mu); s2 += (double)__fmul_rn(d, d);
        d = __fsub_rn(y[j].w, mu); s2 += (double)__fmul_rn(d, d);
    }
#pragma unroll
    for (int o = 16; o; o >>= 1) s2 += __shfl_xor_sync(0xffffffffu, s2, o);
    const float var = (float)(s2 / (double)NC);
    if (lane == 0) {
        muA[row] = mu;
        rsA[row] = __fdiv_rn(1.0f, __fsqrt_rn(__fadd_rn(var, 1e-5f)));
    }
}

// Elementwise LIF step, bit-exact op sequence (no contraction):
#define LIF_STEP(Y, G, B, V, S)                                                \
    {                                                                          \
        const float yy = __fadd_rn(                                            \
            __fmul_rn(__fmul_rn(__fsub_rn((Y), mu), rs), (G)), (B));           \
        (V) = __fadd_rn((V), __fmul_rn(__fsub_rn(yy, (V)), 0.5f));             \
        (S) = ((V) >= 1.0f) ? 1.f : 0.f;                                       \
        (V) = __fmul_rn((V), __fsub_rn(1.0f, (S)));                            \
    }

// ---------------------------------------------------------------------------
// LIF layer 1: pure streaming. One block per (b,l); 384 threads x float4
// cover H=1536. Membrane v in registers across T.
// ---------------------------------------------------------------------------
__global__ __launch_bounds__(384) void lif1_kernel(
    const float* __restrict__ g1, const float* __restrict__ be1) {
    const int bl = blockIdx.x;
    const int bI = bl / Lc, l = bl % Lc;
    const int c = threadIdx.x * 4;
    const float4 gg = *(const float4*)(g1 + c);
    const float4 bb = *(const float4*)(be1 + c);
    float4 v = {0.f, 0.f, 0.f, 0.f};
    const int rbase = bI * Lc + l;
#pragma unroll
    for (int t = 0; t < Tc; t++) {
        const int r = t * (Bc * Lc) + rbase;
        const size_t off = (size_t)r * Hc + c;
        const float4 y = *(const float4*)(g_h1 + off);
        const float mu = g_mu1[r], rs = g_rs1[r];
        float4 sp;
        LIF_STEP(y.x, gg.x, bb.x, v.x, sp.x)
        LIF_STEP(y.y, gg.y, bb.y, v.y, sp.y)
        LIF_STEP(y.z, gg.z, bb.z, v.z, sp.z)
        LIF_STEP(y.w, gg.w, bb.w, v.w, sp.w)
        *(float4*)(g_s1 + off) = sp;
    }
}

// ---------------------------------------------------------------------------
// LIF layer 2 -> final output [B,T,L,D]. 384 threads = 4 rows x 96 lanes x
// float4 (D=384).
// ---------------------------------------------------------------------------
__global__ __launch_bounds__(384) void lif2_kernel(
    const float* __restrict__ g2, const float* __restrict__ be2,
    float* __restrict__ out) {
    const int sub = threadIdx.x / 96;        // 0..3
    const int bl = blockIdx.x * 4 + sub;
    const int bI = bl / Lc, l = bl % Lc;
    const int c = (threadIdx.x % 96) * 4;
    const float4 gg = *(const float4*)(g2 + c);
    const float4 bb = *(const float4*)(be2 + c);
    float4 v = {0.f, 0.f, 0.f, 0.f};
    const int rbase = bI * Lc + l;
#pragma unroll
    for (int t = 0; t < Tc; t++) {
        const int r = t * (Bc * Lc) + rbase;
        const size_t off = (size_t)r * Dc + c;
        const float4 y = *(const float4*)(g_h2 + off);
        const float mu = g_mu2[r], rs = g_rs2[r];
        float4 sp;
        LIF_STEP(y.x, gg.x, bb.x, v.x, sp.x)
        LIF_STEP(y.y, gg.y, bb.y, v.y, sp.y)
        LIF_STEP(y.z, gg.z, bb.z, v.z, sp.z)
        LIF_STEP(y.w, gg.w, bb.w, v.w, sp.w)
        const size_t oo = (size_t)((bI * Tc + t) * Lc + l) * Dc + c;
        *(float4*)(out + oo) = sp;
    }
}

// ---------------------------------------------------------------------------
extern "C" void kernel_launch(void* const* d_in, const int* in_sizes, int n_in,
                              void* d_out, int out_size) {
    const float* x   = (const float*)d_in[0];
    const float* W1  = (const float*)d_in[1];
    const float* b1  = (const float*)d_in[2];
    const float* g1  = (const float*)d_in[3];
    const float* be1 = (const float*)d_in[4];
    const float* W2  = (const float*)d_in[5];
    const float* b2  = (const float*)d_in[6];
    const float* g2  = (const float*)d_in[7];
    const float* be2 = (const float*)d_in[8];
    float* out = (float*)d_out;

    float *mu1, *rs1, *mu2, *rs2, *h1, *h2;
    cudaGetSymbolAddress((void**)&mu1, g_mu1);
    cudaGetSymbolAddress((void**)&rs1, g_rs1);
    cudaGetSymbolAddress((void**)&mu2, g_mu2);
    cudaGetSymbolAddress((void**)&rs2, g_rs2);
    cudaGetSymbolAddress((void**)&h1, g_h1);
    cudaGetSymbolAddress((void**)&h2, g_h2);

    gemm1_kernel<<<dim3(Hc / 128, Mrows / 128), 256>>>(x, W1, b1);
    stats_kernel<Hc><<<Mrows / 8, 256>>>(h1, mu1, rs1);
    lif1_kernel<<<Bc * Lc, 384>>>(g1, be1);
    gemm2_kernel<<<dim3(Dc / 128, Mrows / 128), 256>>>(W2, b2);
    stats_kernel<Dc><<<Mrows / 8, 256>>>(h2, mu2, rs2);
    lif2_kernel<<<(Bc * Lc) / 4, 384>>>(g2, be2, out);
}

// round 5
// speedup vs baseline: 1.6589x; 1.1365x over previous
#include <cuda_runtime.h>
#include <cuda_bf16.h>
#include <math.h>

// Problem dims (fixed by reference setup_inputs)
constexpr int Bc = 32;
constexpr int Tc = 4;
constexpr int Lc = 196;
constexpr int Dc = 384;
constexpr int Hc = 1536;
constexpr int Mrows = Tc * Bc * Lc;   // 25088

// Scratch (device globals; allocation-free per harness rules)
__device__ float g_h1[(size_t)Mrows * Hc];   // pre-LN GEMM1 output  (~154 MB)
__device__ float g_s1[(size_t)Mrows * Hc];   // spikes layer 1       (~154 MB)
__device__ float g_h2[(size_t)Mrows * Dc];   // pre-LN GEMM2 output  (~38 MB)
__device__ float g_mu1[Mrows], g_rs1[Mrows];
__device__ float g_mu2[Mrows], g_rs2[Mrows];

// ---------------------------------------------------------------------------
// GEMM core: 128x128 tile, BK=8, 256 threads, 8x8 per thread (split 4+4 to
// kill smem bank conflicts), double-buffered, 1 sync/iter.
// Bit-exactness contract: each output element is ONE fp32 FMA chain with k
// strictly ascending 0..K-1 (matches the reference einsum), bias added as a
// single separate __fadd_rn at the end.
// blockIdx.x = N-block (small), blockIdx.y = M-block  -> consecutive CTAs
// share the A block and the whole weight matrix through L2.
// Smem rows padded 128->132 floats (132 % 32 == 4) so the STS scatter
// (same column, different k) is conflict-free too.
// ---------------------------------------------------------------------------
#define GEMM_BODY(K_DIM, APTR_EXPR, BPTR_EXPR, BIAS, OUTBASE, OUT_LD)          \
    constexpr int BK = 8;                                                      \
    constexpr int LDS_ = 132;                                                  \
    __shared__ float As[2][BK][LDS_];                                          \
    __shared__ float Bs[2][BK][LDS_];                                          \
    const int tid = threadIdx.x;                                               \
    const int lr = tid >> 1;                                                   \
    const int lc = (tid & 1) * 4;                                              \
    const float* aptr = (APTR_EXPR);                                           \
    const float* bptr = (BPTR_EXPR);                                           \
    const int tx = tid & 15;                                                   \
    const int ty = tid >> 4;                                                   \
    float acc[8][8] = {};                                                      \
    float4 av = *(const float4*)aptr;                                          \
    float4 bv = *(const float4*)bptr;                                          \
    int buf = 0;                                                               \
    As[0][lc + 0][lr] = av.x; As[0][lc + 1][lr] = av.y;                        \
    As[0][lc + 2][lr] = av.z; As[0][lc + 3][lr] = av.w;                        \
    Bs[0][lc + 0][lr] = bv.x; Bs[0][lc + 1][lr] = bv.y;                        \
    Bs[0][lc + 2][lr] = bv.z; Bs[0][lc + 3][lr] = bv.w;                        \
    __syncthreads();                                                           \
    for (int k0 = BK; k0 < (K_DIM) + BK; k0 += BK) {                           \
        const bool more = (k0 < (K_DIM));                                      \
        if (more) {                                                            \
            av = *(const float4*)(aptr + k0);                                  \
            bv = *(const float4*)(bptr + k0);                                  \
        }                                                                      \
        _Pragma("unroll")                                                      \
        for (int k = 0; k < BK; k++) {                                         \
            const float4 a0 = *(const float4*)&As[buf][k][ty * 4];             \
            const float4 a1 = *(const float4*)&As[buf][k][64 + ty * 4];        \
            const float4 b0 = *(const float4*)&Bs[buf][k][tx * 4];             \
            const float4 b1 = *(const float4*)&Bs[buf][k][64 + tx * 4];        \
            const float am[8] = {a0.x, a0.y, a0.z, a0.w, a1.x, a1.y, a1.z, a1.w}; \
            const float bn[8] = {b0.x, b0.y, b0.z, b0.w, b1.x, b1.y, b1.z, b1.w}; \
            _Pragma("unroll")                                                  \
            for (int i = 0; i < 8; i++) {                                      \
                _Pragma("unroll")                                              \
                for (int j = 0; j < 8; j++)                                    \
                    acc[i][j] = __fmaf_rn(am[i], bn[j], acc[i][j]);            \
            }                                                                  \
        }                                                                      \
        if (more) {                                                            \
            buf ^= 1;                                                          \
            As[buf][lc + 0][lr] = av.x; As[buf][lc + 1][lr] = av.y;            \
            As[buf][lc + 2][lr] = av.z; As[buf][lc + 3][lr] = av.w;            \
            Bs[buf][lc + 0][lr] = bv.x; Bs[buf][lc + 1][lr] = bv.y;            \
            Bs[buf][lc + 2][lr] = bv.z; Bs[buf][lc + 3][lr] = bv.w;            \
            __syncthreads();                                                   \
        }                                                                      \
    }                                                                          \
    const int n_base = blockIdx.x * 128;                                       \
    const int m_base = blockIdx.y * 128;                                       \
    const float4 bb0 = *(const float4*)((BIAS) + n_base + tx * 4);             \
    const float4 bb1 = *(const float4*)((BIAS) + n_base + 64 + tx * 4);        \
    _Pragma("unroll")                                                          \
    for (int i = 0; i < 8; i++) {                                              \
        const int m = m_base + ((i < 4) ? (ty * 4 + i) : (64 + ty * 4 + i - 4)); \
        float* o = (OUTBASE) + (size_t)m * (OUT_LD) + n_base;                  \
        float4 o0, o1;                                                         \
        o0.x = __fadd_rn(acc[i][0], bb0.x); o0.y = __fadd_rn(acc[i][1], bb0.y);\
        o0.z = __fadd_rn(acc[i][2], bb0.z); o0.w = __fadd_rn(acc[i][3], bb0.w);\
        o1.x = __fadd_rn(acc[i][4], bb1.x); o1.y = __fadd_rn(acc[i][5], bb1.y);\
        o1.z = __fadd_rn(acc[i][6], bb1.z); o1.w = __fadd_rn(acc[i][7], bb1.w);\
        *(float4*)(o + tx * 4) = o0;                                           \
        *(float4*)(o + 64 + tx * 4) = o1;                                      \
    }

__global__ __launch_bounds__(256) void gemm1_kernel(
    const float* __restrict__ x, const float* __restrict__ W1,
    const float* __restrict__ b1) {
    // A row r = (t*B + b)*L + l maps into x at ((b*T + t)*L + l)*D
    const int r_ = blockIdx.y * 128 + (threadIdx.x >> 1);
    const int l_  = r_ % Lc;
    const int tb_ = r_ / Lc;
    const int bI_ = tb_ % Bc;
    const int tI_ = tb_ / Bc;
    GEMM_BODY(Dc,
              x  + (size_t)((bI_ * Tc + tI_) * Lc + l_) * Dc + ((threadIdx.x & 1) * 4),
              W1 + (size_t)(blockIdx.x * 128 + (threadIdx.x >> 1)) * Dc + ((threadIdx.x & 1) * 4),
              b1, g_h1, Hc)
}

__global__ __launch_bounds__(256) void gemm2_kernel(
    const float* __restrict__ W2, const float* __restrict__ b2) {
    GEMM_BODY(Hc,
              g_s1 + (size_t)(blockIdx.y * 128 + (threadIdx.x >> 1)) * Hc + ((threadIdx.x & 1) * 4),
              W2   + (size_t)(blockIdx.x * 128 + (threadIdx.x >> 1)) * Hc + ((threadIdx.x & 1) * 4),
              b2, g_h2, Dc)
}

// ---------------------------------------------------------------------------
// Row statistics: one warp per row, row held in registers, f64 butterfly
// reduce (no barriers). Same arithmetic as before:
//   mu  = f32( f64sum(y) / N )
//   var = f32( f64sum( f32((y-mu)^2) ) / N )
//   rstd = 1.0f / sqrtf(var + 1e-5f)
// ---------------------------------------------------------------------------
template <int NC>
__global__ __launch_bounds__(256) void stats_kernel(
    const float* __restrict__ src, float* __restrict__ muA,
    float* __restrict__ rsA) {
    const int row = blockIdx.x * 8 + (threadIdx.x >> 5);
    const int lane = threadIdx.x & 31;
    const float* p = src + (size_t)row * NC;
    constexpr int J = NC / 128;
    float4 y[J];
    double s = 0.0;
#pragma unroll
    for (int j = 0; j < J; j++) {
        y[j] = *(const float4*)(p + lane * 4 + j * 128);
        s += (double)y[j].x; s += (double)y[j].y;
        s += (double)y[j].z; s += (double)y[j].w;
    }
#pragma unroll
    for (int o = 16; o; o >>= 1) s += __shfl_xor_sync(0xffffffffu, s, o);
    const float mu = (float)(s / (double)NC);

    double s2 = 0.0;
#pragma unroll
    for (int j = 0; j < J; j++) {
        float d;
        d = __fsub_rn(y[j].x, mu); s2 += (double)__fmul_rn(d, d);
        d = __fsub_rn(y[j].y, mu); s2 += (double)__fmul_rn(d, d);
        d = __fsub_rn(y[j].z, mu); s2 += (double)__fmul_rn(d, d);
        d = __fsub_rn(y[j].w, mu); s2 += (double)__fmul_rn(d, d);
    }
#pragma unroll
    for (int o = 16; o; o >>= 1) s2 += __shfl_xor_sync(0xffffffffu, s2, o);
    const float var = (float)(s2 / (double)NC);
    if (lane == 0) {
        muA[row] = mu;
        rsA[row] = __fdiv_rn(1.0f, __fsqrt_rn(__fadd_rn(var, 1e-5f)));
    }
}

// Elementwise LIF step, bit-exact op sequence (no contraction):
#define LIF_STEP(Y, G, B, V, S)                                                \
    {                                                                          \
        const float yy = __fadd_rn(                                            \
            __fmul_rn(__fmul_rn(__fsub_rn((Y), mu), rs), (G)), (B));           \
        (V) = __fadd_rn((V), __fmul_rn(__fsub_rn(yy, (V)), 0.5f));             \
        (S) = ((V) >= 1.0f) ? 1.f : 0.f;                                       \
        (V) = __fmul_rn((V), __fsub_rn(1.0f, (S)));                            \
    }

// ---------------------------------------------------------------------------
// LIF layer 1: pure streaming. One block per (b,l); 384 threads x float4
// cover H=1536. Membrane v in registers across T.
// ---------------------------------------------------------------------------
__global__ __launch_bounds__(384) void lif1_kernel(
    const float* __restrict__ g1, const float* __restrict__ be1) {
    const int bl = blockIdx.x;
    const int bI = bl / Lc, l = bl % Lc;
    const int c = threadIdx.x * 4;
    const float4 gg = *(const float4*)(g1 + c);
    const float4 bb = *(const float4*)(be1 + c);
    float4 v = {0.f, 0.f, 0.f, 0.f};
    const int rbase = bI * Lc + l;
#pragma unroll
    for (int t = 0; t < Tc; t++) {
        const int r = t * (Bc * Lc) + rbase;
        const size_t off = (size_t)r * Hc + c;
        const float4 y = *(const float4*)(g_h1 + off);
        const float mu = g_mu1[r], rs = g_rs1[r];
        float4 sp;
        LIF_STEP(y.x, gg.x, bb.x, v.x, sp.x)
        LIF_STEP(y.y, gg.y, bb.y, v.y, sp.y)
        LIF_STEP(y.z, gg.z, bb.z, v.z, sp.z)
        LIF_STEP(y.w, gg.w, bb.w, v.w, sp.w)
        *(float4*)(g_s1 + off) = sp;
    }
}

// ---------------------------------------------------------------------------
// LIF layer 2 -> final output [B,T,L,D]. 384 threads = 4 rows x 96 lanes x
// float4 (D=384).
// ---------------------------------------------------------------------------
__global__ __launch_bounds__(384) void lif2_kernel(
    const float* __restrict__ g2, const float* __restrict__ be2,
    float* __restrict__ out) {
    const int sub = threadIdx.x / 96;        // 0..3
    const int bl = blockIdx.x * 4 + sub;
    const int bI = bl / Lc, l = bl % Lc;
    const int c = (threadIdx.x % 96) * 4;
    const float4 gg = *(const float4*)(g2 + c);
    const float4 bb = *(const float4*)(be2 + c);
    float4 v = {0.f, 0.f, 0.f, 0.f};
    const int rbase = bI * Lc + l;
#pragma unroll
    for (int t = 0; t < Tc; t++) {
        const int r = t * (Bc * Lc) + rbase;
        const size_t off = (size_t)r * Dc + c;
        const float4 y = *(const float4*)(g_h2 + off);
        const float mu = g_mu2[r], rs = g_rs2[r];
        float4 sp;
        LIF_STEP(y.x, gg.x, bb.x, v.x, sp.x)
        LIF_STEP(y.y, gg.y, bb.y, v.y, sp.y)
        LIF_STEP(y.z, gg.z, bb.z, v.z, sp.z)
        LIF_STEP(y.w, gg.w, bb.w, v.w, sp.w)
        const size_t oo = (size_t)((bI * Tc + t) * Lc + l) * Dc + c;
        *(float4*)(out + oo) = sp;
    }
}

// ---------------------------------------------------------------------------
extern "C" void kernel_launch(void* const* d_in, const int* in_sizes, int n_in,
                              void* d_out, int out_size) {
    const float* x   = (const float*)d_in[0];
    const float* W1  = (const float*)d_in[1];
    const float* b1  = (const float*)d_in[2];
    const float* g1  = (const float*)d_in[3];
    const float* be1 = (const float*)d_in[4];
    const float* W2  = (const float*)d_in[5];
    const float* b2  = (const float*)d_in[6];
    const float* g2  = (const float*)d_in[7];
    const float* be2 = (const float*)d_in[8];
    float* out = (float*)d_out;

    float *mu1, *rs1, *mu2, *rs2, *h1, *h2;
    cudaGetSymbolAddress((void**)&mu1, g_mu1);
    cudaGetSymbolAddress((void**)&rs1, g_rs1);
    cudaGetSymbolAddress((void**)&mu2, g_mu2);
    cudaGetSymbolAddress((void**)&rs2, g_rs2);
    cudaGetSymbolAddress((void**)&h1, g_h1);
    cudaGetSymbolAddress((void**)&h2, g_h2);

    gemm1_kernel<<<dim3(Hc / 128, Mrows / 128), 256>>>(x, W1, b1);
    stats_kernel<Hc><<<Mrows / 8, 256>>>(h1, mu1, rs1);
    lif1_kernel<<<Bc * Lc, 384>>>(g1, be1);
    gemm2_kernel<<<dim3(Dc / 128, Mrows / 128), 256>>>(W2, b2);
    stats_kernel<Dc><<<Mrows / 8, 256>>>(h2, mu2, rs2);
    lif2_kernel<<<(Bc * Lc) / 4, 384>>>(g2, be2, out);
}